// round 6
// baseline (speedup 1.0000x reference)
#include <cuda_runtime.h>
#include <cstdint>

// ---------------- problem constants ----------------
#define Bn 64
#define Ln 32
#define Dn 768
#define TDn 768
#define Tn 63
#define Sn 32
#define OUTW (Dn + 2 * Tn) // 894

#define K1 3072
#define N1 3072
#define K2 2304
#define N2 3840
#define KSPL1 12
#define KS1 256
#define KSPL2 9
#define KS2 256

// ---------------- device globals ----------------
__device__ float g_W1[K1 * N1];
__device__ float g_W2[K2 * N2];
__device__ float g_A1[Bn * K1];
__device__ float g_A2[Bn * K2];
__device__ float g_C1[KSPL1 * Bn * N1];
__device__ float g_C2[KSPL2 * Bn * N2];
__device__ float g_sh[Bn * Sn * Dn];
__device__ float g_sc[Bn * Sn * Dn];
__device__ float g_trkc[Bn * TDn];
__device__ int g_bufpos[Tn * Bn];
__device__ int g_p1[Tn * Bn];
__device__ int g_p2[Tn * Bn];
__device__ int g_wpos[Tn * Bn];
__device__ int g_op[Tn * Bn];
__device__ int g_fpos[Bn];

// ---------------- helpers ----------------
__device__ __forceinline__ float to_tf32(float x) {
    uint32_t y;
    asm("cvt.rna.tf32.f32 %0, %1;" : "=r"(y) : "f"(x));
    return __uint_as_float(y);
}
__device__ __forceinline__ float sigm(float x) { return 1.f / (1.f + expf(-x)); }

// ---------------- prologue: precompute shift/reduce indices ----------------
__global__ void idx_kernel(const int* __restrict__ tr) {
    int b = threadIdx.x;
    if (b >= Bn) return;
    int ptr = 0, buft = 0;
    for (int t = 0; t < Tn; t++) {
        int op = tr[b * Tn + t];
        int bp = Ln - 1 - buft;
        bp = bp < 0 ? 0 : (bp > Ln - 1 ? Ln - 1 : bp);
        g_bufpos[t * Bn + b] = bp;
        g_p1[t * Bn + b] = (ptr > 0) ? min(ptr - 1, Sn - 1) : -1;
        g_p2[t * Bn + b] = (ptr > 1) ? min(ptr - 2, Sn - 1) : -1;
        int wp = (op == 0) ? ptr : ptr - 2;
        wp = wp < 0 ? 0 : (wp > Sn - 1 ? Sn - 1 : wp);
        g_wpos[t * Bn + b] = wp;
        g_op[t * Bn + b] = op;
        ptr += (op == 0) ? 1 : ((op == 1) ? -1 : 0);
        buft += (op == 0) ? 1 : 0;
    }
    int fp = ptr - 1;
    fp = fp < 0 ? 0 : (fp > Sn - 1 ? Sn - 1 : fp);
    g_fpos[b] = fp;
}

// ---------------- prologue: concat + tf32-round weights ----------------
__global__ void conv_w(const float* __restrict__ Wbuf, const float* __restrict__ Ws1,
                       const float* __restrict__ Ws2, const float* __restrict__ Wlat,
                       const float* __restrict__ Wl, const float* __restrict__ Wr,
                       const float* __restrict__ Wt) {
    const int total1 = K1 * N1;
    const int total2 = K2 * N2;
    for (int i = blockIdx.x * blockDim.x + threadIdx.x; i < total1 + total2;
         i += gridDim.x * blockDim.x) {
        if (i < total1) {
            int k = i / N1, n = i - k * N1;
            const float* src = (k < 768) ? Wbuf : (k < 1536) ? Ws1 : (k < 2304) ? Ws2 : Wlat;
            g_W1[i] = to_tf32(src[(k % 768) * N1 + n]);
        } else {
            int j = i - total1;
            int k = j / N2, n = j - k * N2;
            const float* src = (k < 768) ? Wl : (k < 1536) ? Wr : Wt;
            g_W2[j] = to_tf32(src[(k % 768) * N2 + n]);
        }
    }
}

// ---------------- prologue: zero state + build A1/A2 for step 0 ----------------
__global__ void init_kernel(const float* __restrict__ buffer_h) {
    const int n1 = Bn * Sn * Dn;
    const int n2 = 2 * n1;
    const int n3 = n2 + Bn * TDn;
    const int n4 = n3 + Bn * K1;
    const int n5 = n4 + Bn * K2;
    for (int i = blockIdx.x * blockDim.x + threadIdx.x; i < n5; i += gridDim.x * blockDim.x) {
        if (i < n1) g_sh[i] = 0.f;
        else if (i < n2) g_sc[i - n1] = 0.f;
        else if (i < n3) g_trkc[i - n2] = 0.f;
        else if (i < n4) {
            int j = i - n3;
            int b = j / K1, k = j - b * K1;
            g_A1[j] = (k < 768) ? to_tf32(buffer_h[b * Ln * Dn + (Ln - 1) * Dn + k]) : 0.f;
        } else {
            g_A2[i - n4] = 0.f;
        }
    }
}

// ---------------- split-K TF32 GEMM: C[ky][64][N] = A[64, KS] @ W[KS, N] ----------------
// block tile 64(M) x 128(N) x 32(K); 8 warps = 2(m) x 4(n), warp tile 32x32
// Tiles loaded with cp.async.bulk (row-wise) + mbarrier complete_tx pipeline.
#define BM 64
#define BN 128
#define BK 32
#define A_ST 36   // A smem stride (BK + 4 pad)  -> 144 B, 16B multiple
#define W_ST 132  // W smem stride (BN + 4 pad)  -> 528 B, 16B multiple
#define ASZ (BM * A_ST)         // 2304 floats
#define WSZ (BK * W_ST)         // 4224 floats
#define STG_FLT (ASZ + WSZ)     // 6528 floats / stage
#define NSTAGE 4
#define STAGE_BYTES (BM * BK * 4 + BK * BN * 4) // 8192 + 16384 = 24576
#define MBAR_FLT 16             // 64 B reserved at smem start for 4 mbarriers

__device__ __forceinline__ void bulkcp(uint32_t dst, const void* src, int bytes, uint32_t mbar) {
    asm volatile(
        "cp.async.bulk.shared::cluster.global.mbarrier::complete_tx::bytes [%0], [%1], %2, [%3];"
        :: "r"(dst), "l"(src), "r"(bytes), "r"(mbar) : "memory");
}

__device__ __forceinline__ void mbar_expect(uint32_t mbar, uint32_t bytes) {
    asm volatile("mbarrier.arrive.expect_tx.shared.b64 _, [%0], %1;"
                 :: "r"(mbar), "r"(bytes) : "memory");
}

__device__ __forceinline__ void mbar_wait(uint32_t mbar, uint32_t parity) {
    asm volatile(
        "{\n\t"
        ".reg .pred P;\n\t"
        "WAIT_%=:\n\t"
        "mbarrier.try_wait.parity.shared.b64 P, [%0], %1;\n\t"
        "@P bra DONE_%=;\n\t"
        "bra WAIT_%=;\n\t"
        "DONE_%=:\n\t"
        "}"
        :: "r"(mbar), "r"(parity) : "memory");
}

__device__ __forceinline__ void produce_stage(float* stg, uint32_t mbar,
                                              const float* A, const float* W,
                                              int ldA, int N, int kb, int n0, int tid) {
    if (tid == 0) mbar_expect(mbar, STAGE_BYTES);
    if (tid < BM) {
        // A rows: 64 copies of 128 B
        uint32_t dst = (uint32_t)__cvta_generic_to_shared(stg + tid * A_ST);
        bulkcp(dst, A + (size_t)tid * ldA + kb, BK * 4, mbar);
    } else if (tid < BM + BK) {
        // W rows: 32 copies of 512 B
        int r = tid - BM;
        uint32_t dst = (uint32_t)__cvta_generic_to_shared(stg + ASZ + r * W_ST);
        bulkcp(dst, W + (size_t)(kb + r) * N + n0, BN * 4, mbar);
    }
}

__global__ void __launch_bounds__(256, 2) gemm_tf32(int which) {
    const float* A;
    const float* W;
    float* C;
    int ldA, N, KS;
    if (which == 1) { A = g_A1; W = g_W1; C = g_C1; ldA = K1; N = N1; KS = KS1; }
    else            { A = g_A2; W = g_W2; C = g_C2; ldA = K2; N = N2; KS = KS2; }

    extern __shared__ float sm[];
    float* stg_base = sm + MBAR_FLT;
    uint32_t mbar0 = (uint32_t)__cvta_generic_to_shared(sm);

    const int tid = threadIdx.x;
    const int n0 = blockIdx.x * BN;
    const int kbase0 = blockIdx.y * KS;
    const int niter = KS / BK;   // 8

    // init mbarriers (count=1: the expect_tx arrival)
    if (tid == 0) {
#pragma unroll
        for (int s = 0; s < NSTAGE; s++)
            asm volatile("mbarrier.init.shared.b64 [%0], 1;" :: "r"(mbar0 + s * 8) : "memory");
        asm volatile("fence.proxy.async.shared::cta;" ::: "memory");
    }
    __syncthreads();

    const int lane = tid & 31, w = tid >> 5;
    const int wm = w >> 2, wn = w & 3;      // 2 x 4 warp grid
    const int g = lane >> 2, tg = lane & 3;

    float acc[2][4][4];
#pragma unroll
    for (int mt = 0; mt < 2; mt++)
#pragma unroll
        for (int nt = 0; nt < 4; nt++)
#pragma unroll
            for (int j = 0; j < 4; j++) acc[mt][nt][j] = 0.f;

    // prologue: issue stages 0..NSTAGE-2
#pragma unroll
    for (int s = 0; s < NSTAGE - 1; s++)
        produce_stage(stg_base + s * STG_FLT, mbar0 + s * 8, A, W, ldA, N,
                      kbase0 + s * BK, n0, tid);

    for (int it = 0; it < niter; ++it) {
        __syncthreads();  // slot (it+NSTAGE-1)%NSTAGE free (compute of it-1 done everywhere)

        int j = it + NSTAGE - 1;
        if (j < niter) {
            int s = j % NSTAGE;
            produce_stage(stg_base + s * STG_FLT, mbar0 + s * 8, A, W, ldA, N,
                          kbase0 + j * BK, n0, tid);
        }

        // wait for stage it
        mbar_wait(mbar0 + (it % NSTAGE) * 8, (it / NSTAGE) & 1);

        const float* as = stg_base + (it % NSTAGE) * STG_FLT + (wm * 32) * A_ST;
        const float* ws = stg_base + (it % NSTAGE) * STG_FLT + ASZ + wn * 32;
#pragma unroll
        for (int ks = 0; ks < 4; ks++) {
            int kk = ks * 8;
            uint32_t a[2][4];
#pragma unroll
            for (int mt = 0; mt < 2; mt++) {
                const float* ar = as + (mt * 16) * A_ST;
                a[mt][0] = __float_as_uint(ar[g * A_ST + kk + tg]);
                a[mt][1] = __float_as_uint(ar[(g + 8) * A_ST + kk + tg]);
                a[mt][2] = __float_as_uint(ar[g * A_ST + kk + tg + 4]);
                a[mt][3] = __float_as_uint(ar[(g + 8) * A_ST + kk + tg + 4]);
            }
            uint32_t bfr[4][2];
#pragma unroll
            for (int nt = 0; nt < 4; nt++) {
                bfr[nt][0] = __float_as_uint(ws[(kk + tg) * W_ST + nt * 8 + g]);
                bfr[nt][1] = __float_as_uint(ws[(kk + tg + 4) * W_ST + nt * 8 + g]);
            }
#pragma unroll
            for (int mt = 0; mt < 2; mt++)
#pragma unroll
                for (int nt = 0; nt < 4; nt++) {
                    asm volatile(
                        "mma.sync.aligned.m16n8k8.row.col.f32.tf32.tf32.f32 "
                        "{%0,%1,%2,%3}, {%4,%5,%6,%7}, {%8,%9}, {%0,%1,%2,%3};"
                        : "+f"(acc[mt][nt][0]), "+f"(acc[mt][nt][1]),
                          "+f"(acc[mt][nt][2]), "+f"(acc[mt][nt][3])
                        : "r"(a[mt][0]), "r"(a[mt][1]), "r"(a[mt][2]), "r"(a[mt][3]),
                          "r"(bfr[nt][0]), "r"(bfr[nt][1]));
                }
        }
    }

    // epilogue: write split-K partial
    float* Cp = C + (size_t)blockIdx.y * (Bn * N) + n0;
#pragma unroll
    for (int mt = 0; mt < 2; mt++) {
        int row0 = wm * 32 + mt * 16 + g;
#pragma unroll
        for (int nt = 0; nt < 4; nt++) {
            int col = wn * 32 + nt * 8 + tg * 2;
            *(float2*)(Cp + (size_t)row0 * N + col) = make_float2(acc[mt][nt][0], acc[mt][nt][1]);
            *(float2*)(Cp + (size_t)(row0 + 8) * N + col) = make_float2(acc[mt][nt][2], acc[mt][nt][3]);
        }
    }
}

// ---------------- per-step: tracker LSTM update + logits ----------------
__global__ void tracker_kernel(int t, const float* __restrict__ b_lat,
                               const float* __restrict__ Wtr, const float* __restrict__ btr,
                               float* __restrict__ out) {
    int b = blockIdx.x;
    int d = threadIdx.x;
    float a = b_lat[d], ii = b_lat[d + 768], ff = b_lat[d + 1536], oo = b_lat[d + 2304];
#pragma unroll
    for (int p = 0; p < KSPL1; p++) {
        const float* cp = g_C1 + (size_t)p * Bn * N1 + (size_t)b * N1;
        a  += cp[d];
        ii += cp[d + 768];
        ff += cp[d + 1536];
        oo += cp[d + 2304];
    }
    float c = tanhf(a) * sigm(ii) + sigm(ff) * g_trkc[b * TDn + d];
    float h = sigm(oo) * tanhf(c);
    g_trkc[b * TDn + d] = c;
    float hr = to_tf32(h);
    g_A2[b * K2 + 1536 + d] = hr;
    g_A1[b * K1 + 2304 + d] = hr;

    float l0 = h * Wtr[d * 2];
    float l1 = h * Wtr[d * 2 + 1];
#pragma unroll
    for (int off = 16; off; off >>= 1) {
        l0 += __shfl_down_sync(0xffffffffu, l0, off);
        l1 += __shfl_down_sync(0xffffffffu, l1, off);
    }
    __shared__ float red[24][2];
    int wid = d >> 5;
    if ((d & 31) == 0) { red[wid][0] = l0; red[wid][1] = l1; }
    __syncthreads();
    if (d < 32) {
        float r0 = (d < 24) ? red[d][0] : 0.f;
        float r1 = (d < 24) ? red[d][1] : 0.f;
#pragma unroll
        for (int off = 16; off; off >>= 1) {
            r0 += __shfl_down_sync(0xffffffffu, r0, off);
            r1 += __shfl_down_sync(0xffffffffu, r1, off);
        }
        if (d == 0) {
            out[(size_t)b * OUTW + Dn + 2 * t]     = r0 + btr[0];
            out[(size_t)b * OUTW + Dn + 2 * t + 1] = r1 + btr[1];
        }
    }
}

// ---------------- per-step: compose + stack update + next-step gather ----------------
__global__ void compose_kernel(int t, const float* __restrict__ buffer_h,
                               const float* __restrict__ buffer_c,
                               const float* __restrict__ b_left) {
    int b = blockIdx.x;
    int d = threadIdx.x;
    int base = t * Bn + b;
    int p1 = g_p1[base], p2 = g_p2[base], wp = g_wpos[base], op = g_op[base], bp = g_bufpos[base];

    float s1c = (p1 >= 0) ? g_sc[(b * Sn + p1) * Dn + d] : 0.f;
    float s2c = (p2 >= 0) ? g_sc[(b * Sn + p2) * Dn + d] : 0.f;

    float gi = b_left[d], gfl = b_left[d + 768], gfr = b_left[d + 1536];
    float go = b_left[d + 2304], gg = b_left[d + 3072];
#pragma unroll
    for (int p = 0; p < KSPL2; p++) {
        const float* cp = g_C2 + (size_t)p * Bn * N2 + (size_t)b * N2;
        gi  += cp[d];
        gfl += cp[d + 768];
        gfr += cp[d + 1536];
        go  += cp[d + 2304];
        gg  += cp[d + 3072];
    }

    float cc = sigm(gfl) * s2c + sigm(gfr) * s1c + sigm(gi) * tanhf(gg);
    float ch = sigm(go) * tanhf(cc);

    float wh, wc;
    if (op == 0) {
        wh = buffer_h[(b * Ln + bp) * Dn + d];
        wc = buffer_c[(b * Ln + bp) * Dn + d];
    } else if (op == 1) {
        wh = ch; wc = cc;
    } else {
        wh = g_sh[(b * Sn + wp) * Dn + d];
        wc = g_sc[(b * Sn + wp) * Dn + d];
    }
    g_sh[(b * Sn + wp) * Dn + d] = wh;
    g_sc[(b * Sn + wp) * Dn + d] = wc;

    if (t + 1 < Tn) {
        int nb = (t + 1) * Bn + b;
        int nbp = g_bufpos[nb], np1 = g_p1[nb], np2 = g_p2[nb];
        float nbh = to_tf32(buffer_h[(b * Ln + nbp) * Dn + d]);
        float ns1 = (np1 >= 0) ? to_tf32(g_sh[(b * Sn + np1) * Dn + d]) : 0.f;
        float ns2 = (np2 >= 0) ? to_tf32(g_sh[(b * Sn + np2) * Dn + d]) : 0.f;
        g_A1[b * K1 + d] = nbh;
        g_A1[b * K1 + 768 + d] = ns1;
        g_A1[b * K1 + 1536 + d] = ns2;
        g_A2[b * K2 + d] = ns2;
        g_A2[b * K2 + 768 + d] = ns1;
    }
}

// ---------------- epilogue: final_h ----------------
__global__ void final_kernel(float* __restrict__ out) {
    int b = blockIdx.x, d = threadIdx.x;
    out[(size_t)b * OUTW + d] = g_sh[(b * Sn + g_fpos[b]) * Dn + d];
}

// ---------------- launch ----------------
extern "C" void kernel_launch(void* const* d_in, const int* in_sizes, int n_in,
                              void* d_out, int out_size) {
    const float* buffer_h = (const float*)d_in[0];
    const float* buffer_c = (const float*)d_in[1];
    const int* transitions = (const int*)d_in[2];
    const float* W_buf  = (const float*)d_in[3];
    const float* W_s1   = (const float*)d_in[4];
    const float* W_s2   = (const float*)d_in[5];
    const float* W_lat  = (const float*)d_in[6];
    const float* b_lat  = (const float*)d_in[7];
    const float* W_trans = (const float*)d_in[8];
    const float* b_trans = (const float*)d_in[9];
    const float* W_left = (const float*)d_in[10];
    const float* b_left = (const float*)d_in[11];
    const float* W_right = (const float*)d_in[12];
    const float* W_track = (const float*)d_in[13];
    float* out = (float*)d_out;

    const size_t smem = (MBAR_FLT + (size_t)NSTAGE * STG_FLT) * sizeof(float); // 104512 B
    cudaFuncSetAttribute(gemm_tf32, cudaFuncAttributeMaxDynamicSharedMemorySize, (int)smem);

    conv_w<<<1024, 256>>>(W_buf, W_s1, W_s2, W_lat, W_left, W_right, W_track);
    idx_kernel<<<1, 64>>>(transitions);
    init_kernel<<<512, 256>>>(buffer_h);

    for (int t = 0; t < Tn; t++) {
        gemm_tf32<<<dim3(N1 / BN, KSPL1), 256, smem>>>(1);
        tracker_kernel<<<Bn, Dn>>>(t, b_lat, W_trans, b_trans, out);
        gemm_tf32<<<dim3(N2 / BN, KSPL2), 256, smem>>>(2);
        compose_kernel<<<Bn, Dn>>>(t, buffer_h, buffer_c, b_left);
    }
    final_kernel<<<Bn, Dn>>>(out);
}

// round 7
// speedup vs baseline: 1.1482x; 1.1482x over previous
#include <cuda_runtime.h>
#include <cstdint>

// ---------------- problem constants ----------------
#define Bn 64
#define Ln 32
#define Dn 768
#define TDn 768
#define Tn 63
#define Sn 32
#define OUTW (Dn + 2 * Tn) // 894

#define K1 3072
#define N1 3072
#define K2 2304
#define N2 3840
#define KSPL1 12
#define KSPL2 9
#define KS 256          // K-slice per CTA (both GEMMs)

// ---------------- device globals ----------------
// W packed in MMA-fragment-linear layout (see pack mapping in conv_w)
__device__ float g_W1[K1 * N1];
__device__ float g_W2[K2 * N2];
__device__ float g_A1[Bn * K1];
__device__ float g_A2[Bn * K2];
__device__ float g_C1[KSPL1 * Bn * N1];
__device__ float g_C2[KSPL2 * Bn * N2];
__device__ float g_sh[Bn * Sn * Dn];
__device__ float g_sc[Bn * Sn * Dn];
__device__ float g_trkc[Bn * TDn];
__device__ int g_bufpos[Tn * Bn];
__device__ int g_p1[Tn * Bn];
__device__ int g_p2[Tn * Bn];
__device__ int g_wpos[Tn * Bn];
__device__ int g_op[Tn * Bn];
__device__ int g_fpos[Bn];

// ---------------- helpers ----------------
__device__ __forceinline__ float to_tf32(float x) {
    uint32_t y;
    asm("cvt.rna.tf32.f32 %0, %1;" : "=r"(y) : "f"(x));
    return __uint_as_float(y);
}
__device__ __forceinline__ float sigm(float x) { return 1.f / (1.f + expf(-x)); }

// ---------------- prologue: precompute shift/reduce indices ----------------
__global__ void idx_kernel(const int* __restrict__ tr) {
    int b = threadIdx.x;
    if (b >= Bn) return;
    int ptr = 0, buft = 0;
    for (int t = 0; t < Tn; t++) {
        int op = tr[b * Tn + t];
        int bp = Ln - 1 - buft;
        bp = bp < 0 ? 0 : (bp > Ln - 1 ? Ln - 1 : bp);
        g_bufpos[t * Bn + b] = bp;
        g_p1[t * Bn + b] = (ptr > 0) ? min(ptr - 1, Sn - 1) : -1;
        g_p2[t * Bn + b] = (ptr > 1) ? min(ptr - 2, Sn - 1) : -1;
        int wp = (op == 0) ? ptr : ptr - 2;
        wp = wp < 0 ? 0 : (wp > Sn - 1 ? Sn - 1 : wp);
        g_wpos[t * Bn + b] = wp;
        g_op[t * Bn + b] = op;
        ptr += (op == 0) ? 1 : ((op == 1) ? -1 : 0);
        buft += (op == 0) ? 1 : 0;
    }
    int fp = ptr - 1;
    fp = fp < 0 ? 0 : (fp > Sn - 1 ? Sn - 1 : fp);
    g_fpos[b] = fp;
}

// ---------------- prologue: concat + tf32-round + MMA-fragment pack ----------------
// Packed layout: matrix [K, N] row-major source -> blocks [n_blk][k0_idx] of
// 256 floats (8 k x 32 n). Within a block, float4 j (j = half*32 + lane):
//   e in 0..3 of the float4:  nt = half*2 + (e>>1), bsel = e&1
//   src k = k0_idx*8 + (lane&3) + bsel*4,  src n = n_blk*32 + nt*8 + (lane>>2)
// A warp streaming its 32-column strip reads 2 contiguous LDG.128 per k0 block.
__device__ __forceinline__ int pack_src(int p, int K, int N) {
    int nblk = p / (K * 32);
    int r = p - nblk * K * 32;
    int k0 = r >> 8;
    int q = r & 255;
    int j = q >> 2, e = q & 3;
    int half = j >> 5, lane = j & 31;
    int g = lane >> 2, tg = lane & 3;
    int nt = half * 2 + (e >> 1);
    int ksrc = k0 * 8 + tg + ((e & 1) ? 4 : 0);
    int nsrc = nblk * 32 + nt * 8 + g;
    return ksrc * N + nsrc;
}

__global__ void conv_w(const float* __restrict__ Wbuf, const float* __restrict__ Ws1,
                       const float* __restrict__ Ws2, const float* __restrict__ Wlat,
                       const float* __restrict__ Wl, const float* __restrict__ Wr,
                       const float* __restrict__ Wt) {
    const int total1 = K1 * N1;
    const int total2 = K2 * N2;
    for (int i = blockIdx.x * blockDim.x + threadIdx.x; i < total1 + total2;
         i += gridDim.x * blockDim.x) {
        if (i < total1) {
            int s = pack_src(i, K1, N1);
            int k = s / N1, n = s - k * N1;
            const float* src = (k < 768) ? Wbuf : (k < 1536) ? Ws1 : (k < 2304) ? Ws2 : Wlat;
            g_W1[i] = to_tf32(src[(k % 768) * N1 + n]);
        } else {
            int j = i - total1;
            int s = pack_src(j, K2, N2);
            int k = s / N2, n = s - k * N2;
            const float* src = (k < 768) ? Wl : (k < 1536) ? Wr : Wt;
            g_W2[j] = to_tf32(src[(k % 768) * N2 + n]);
        }
    }
}

// ---------------- prologue: zero state + build A1/A2 for step 0 ----------------
__global__ void init_kernel(const float* __restrict__ buffer_h) {
    const int n1 = Bn * Sn * Dn;
    const int n2 = 2 * n1;
    const int n3 = n2 + Bn * TDn;
    const int n4 = n3 + Bn * K1;
    const int n5 = n4 + Bn * K2;
    for (int i = blockIdx.x * blockDim.x + threadIdx.x; i < n5; i += gridDim.x * blockDim.x) {
        if (i < n1) g_sh[i] = 0.f;
        else if (i < n2) g_sc[i - n1] = 0.f;
        else if (i < n3) g_trkc[i - n2] = 0.f;
        else if (i < n4) {
            int j = i - n3;
            int b = j / K1, k = j - b * K1;
            g_A1[j] = (k < 768) ? to_tf32(buffer_h[b * Ln * Dn + (Ln - 1) * Dn + k]) : 0.f;
        } else {
            g_A2[i - n4] = 0.f;
        }
    }
}

// ---------------- split-K TF32 GEMM, W streamed from global (packed) ----------------
// block tile 64(M) x 128(N) x KS(256); 8 warps = 2(m) x 4(n), warp tile 32x32.
// A tile (64 x 256) loaded to smem once; mainloop has NO barriers.
#define BM 64
#define BN 128
#define A_ST 260                 // KS + 4 pad (floats)
#define ASZ (BM * A_ST)          // 16640 floats = 66560 B

__device__ __forceinline__ void cp16(uint32_t dst, const void* src) {
    asm volatile("cp.async.cg.shared.global [%0], [%1], 16;" :: "r"(dst), "l"(src));
}

__global__ void __launch_bounds__(256, 2) gemm_tf32(int which) {
    const float* A;
    const float* Wp;
    float* C;
    int ldA, N, Ktot;
    if (which == 1) { A = g_A1; Wp = g_W1; C = g_C1; ldA = K1; N = N1; Ktot = K1; }
    else            { A = g_A2; Wp = g_W2; C = g_C2; ldA = K2; N = N2; Ktot = K2; }

    extern __shared__ float sm[];

    const int tid = threadIdx.x;
    const int kbase0 = blockIdx.y * KS;

    // load A tile 64 x 256 into smem (once)
#pragma unroll
    for (int j = 0; j < 16; j++) {
        int idx = tid + j * 256;
        int r = idx >> 6;               // row 0..63
        int c = (idx & 63) << 2;        // col 0..252
        cp16((uint32_t)__cvta_generic_to_shared(sm + r * A_ST + c), A + (size_t)r * ldA + kbase0 + c);
    }
    asm volatile("cp.async.commit_group;");
    asm volatile("cp.async.wait_group 0;");
    __syncthreads();

    const int lane = tid & 31, w = tid >> 5;
    const int wm = w >> 2, wn = w & 3;      // 2 x 4 warp grid
    const int g = lane >> 2, tg = lane & 3;

    // warp's packed W stream: n_blk = blockIdx.x*4 + wn
    const float4* wp = (const float4*)(Wp + ((size_t)(blockIdx.x * 4 + wn) * Ktot + kbase0) * 32);
    // per k0-step: block of 64 float4; this thread reads [lane] and [32+lane]

    float acc[2][4][4];
#pragma unroll
    for (int mt = 0; mt < 2; mt++)
#pragma unroll
        for (int nt = 0; nt < 4; nt++)
#pragma unroll
            for (int j = 0; j < 4; j++) acc[mt][nt][j] = 0.f;

    const float* as = sm + (wm * 32) * A_ST;

    // prefetch first block
    float4 nb01 = wp[lane];
    float4 nb23 = wp[32 + lane];

#pragma unroll 4
    for (int it = 0; it < KS / 8; ++it) {
        float4 b01 = nb01, b23 = nb23;
        if (it + 1 < KS / 8) {
            const float4* nxt = wp + (it + 1) * 64;
            nb01 = nxt[lane];
            nb23 = nxt[32 + lane];
        }
        int kk = it * 8;
        uint32_t a[2][4];
#pragma unroll
        for (int mt = 0; mt < 2; mt++) {
            const float* ar = as + (mt * 16) * A_ST;
            a[mt][0] = __float_as_uint(ar[g * A_ST + kk + tg]);
            a[mt][1] = __float_as_uint(ar[(g + 8) * A_ST + kk + tg]);
            a[mt][2] = __float_as_uint(ar[g * A_ST + kk + tg + 4]);
            a[mt][3] = __float_as_uint(ar[(g + 8) * A_ST + kk + tg + 4]);
        }
        uint32_t bfr[4][2];
        bfr[0][0] = __float_as_uint(b01.x); bfr[0][1] = __float_as_uint(b01.y);
        bfr[1][0] = __float_as_uint(b01.z); bfr[1][1] = __float_as_uint(b01.w);
        bfr[2][0] = __float_as_uint(b23.x); bfr[2][1] = __float_as_uint(b23.y);
        bfr[3][0] = __float_as_uint(b23.z); bfr[3][1] = __float_as_uint(b23.w);
#pragma unroll
        for (int mt = 0; mt < 2; mt++)
#pragma unroll
            for (int nt = 0; nt < 4; nt++) {
                asm volatile(
                    "mma.sync.aligned.m16n8k8.row.col.f32.tf32.tf32.f32 "
                    "{%0,%1,%2,%3}, {%4,%5,%6,%7}, {%8,%9}, {%0,%1,%2,%3};"
                    : "+f"(acc[mt][nt][0]), "+f"(acc[mt][nt][1]),
                      "+f"(acc[mt][nt][2]), "+f"(acc[mt][nt][3])
                    : "r"(a[mt][0]), "r"(a[mt][1]), "r"(a[mt][2]), "r"(a[mt][3]),
                      "r"(bfr[nt][0]), "r"(bfr[nt][1]));
            }
    }

    // epilogue: write split-K partial
    float* Cp = C + (size_t)blockIdx.y * (Bn * N) + blockIdx.x * BN;
#pragma unroll
    for (int mt = 0; mt < 2; mt++) {
        int row0 = wm * 32 + mt * 16 + g;
#pragma unroll
        for (int nt = 0; nt < 4; nt++) {
            int col = wn * 32 + nt * 8 + tg * 2;
            *(float2*)(Cp + (size_t)row0 * N + col) = make_float2(acc[mt][nt][0], acc[mt][nt][1]);
            *(float2*)(Cp + (size_t)(row0 + 8) * N + col) = make_float2(acc[mt][nt][2], acc[mt][nt][3]);
        }
    }
}

// ---------------- per-step: tracker LSTM update + logits ----------------
__global__ void tracker_kernel(int t, const float* __restrict__ b_lat,
                               const float* __restrict__ Wtr, const float* __restrict__ btr,
                               float* __restrict__ out) {
    int b = blockIdx.x;
    int d = threadIdx.x;
    float a = b_lat[d], ii = b_lat[d + 768], ff = b_lat[d + 1536], oo = b_lat[d + 2304];
#pragma unroll
    for (int p = 0; p < KSPL1; p++) {
        const float* cp = g_C1 + (size_t)p * Bn * N1 + (size_t)b * N1;
        a  += cp[d];
        ii += cp[d + 768];
        ff += cp[d + 1536];
        oo += cp[d + 2304];
    }
    float c = tanhf(a) * sigm(ii) + sigm(ff) * g_trkc[b * TDn + d];
    float h = sigm(oo) * tanhf(c);
    g_trkc[b * TDn + d] = c;
    float hr = to_tf32(h);
    g_A2[b * K2 + 1536 + d] = hr;
    g_A1[b * K1 + 2304 + d] = hr;

    float l0 = h * Wtr[d * 2];
    float l1 = h * Wtr[d * 2 + 1];
#pragma unroll
    for (int off = 16; off; off >>= 1) {
        l0 += __shfl_down_sync(0xffffffffu, l0, off);
        l1 += __shfl_down_sync(0xffffffffu, l1, off);
    }
    __shared__ float red[24][2];
    int wid = d >> 5;
    if ((d & 31) == 0) { red[wid][0] = l0; red[wid][1] = l1; }
    __syncthreads();
    if (d < 32) {
        float r0 = (d < 24) ? red[d][0] : 0.f;
        float r1 = (d < 24) ? red[d][1] : 0.f;
#pragma unroll
        for (int off = 16; off; off >>= 1) {
            r0 += __shfl_down_sync(0xffffffffu, r0, off);
            r1 += __shfl_down_sync(0xffffffffu, r1, off);
        }
        if (d == 0) {
            out[(size_t)b * OUTW + Dn + 2 * t]     = r0 + btr[0];
            out[(size_t)b * OUTW + Dn + 2 * t + 1] = r1 + btr[1];
        }
    }
}

// ---------------- per-step: compose + stack update + next-step gather ----------------
__global__ void compose_kernel(int t, const float* __restrict__ buffer_h,
                               const float* __restrict__ buffer_c,
                               const float* __restrict__ b_left) {
    int b = blockIdx.x;
    int d = threadIdx.x;
    int base = t * Bn + b;
    int p1 = g_p1[base], p2 = g_p2[base], wp = g_wpos[base], op = g_op[base], bp = g_bufpos[base];

    float s1c = (p1 >= 0) ? g_sc[(b * Sn + p1) * Dn + d] : 0.f;
    float s2c = (p2 >= 0) ? g_sc[(b * Sn + p2) * Dn + d] : 0.f;

    float gi = b_left[d], gfl = b_left[d + 768], gfr = b_left[d + 1536];
    float go = b_left[d + 2304], gg = b_left[d + 3072];
#pragma unroll
    for (int p = 0; p < KSPL2; p++) {
        const float* cp = g_C2 + (size_t)p * Bn * N2 + (size_t)b * N2;
        gi  += cp[d];
        gfl += cp[d + 768];
        gfr += cp[d + 1536];
        go  += cp[d + 2304];
        gg  += cp[d + 3072];
    }

    float cc = sigm(gfl) * s2c + sigm(gfr) * s1c + sigm(gi) * tanhf(gg);
    float ch = sigm(go) * tanhf(cc);

    float wh, wc;
    if (op == 0) {
        wh = buffer_h[(b * Ln + bp) * Dn + d];
        wc = buffer_c[(b * Ln + bp) * Dn + d];
    } else if (op == 1) {
        wh = ch; wc = cc;
    } else {
        wh = g_sh[(b * Sn + wp) * Dn + d];
        wc = g_sc[(b * Sn + wp) * Dn + d];
    }
    g_sh[(b * Sn + wp) * Dn + d] = wh;
    g_sc[(b * Sn + wp) * Dn + d] = wc;

    if (t + 1 < Tn) {
        int nb = (t + 1) * Bn + b;
        int nbp = g_bufpos[nb], np1 = g_p1[nb], np2 = g_p2[nb];
        float nbh = to_tf32(buffer_h[(b * Ln + nbp) * Dn + d]);
        float ns1 = (np1 >= 0) ? to_tf32(g_sh[(b * Sn + np1) * Dn + d]) : 0.f;
        float ns2 = (np2 >= 0) ? to_tf32(g_sh[(b * Sn + np2) * Dn + d]) : 0.f;
        g_A1[b * K1 + d] = nbh;
        g_A1[b * K1 + 768 + d] = ns1;
        g_A1[b * K1 + 1536 + d] = ns2;
        g_A2[b * K2 + d] = ns2;
        g_A2[b * K2 + 768 + d] = ns1;
    }
}

// ---------------- epilogue: final_h ----------------
__global__ void final_kernel(float* __restrict__ out) {
    int b = blockIdx.x, d = threadIdx.x;
    out[(size_t)b * OUTW + d] = g_sh[(b * Sn + g_fpos[b]) * Dn + d];
}

// ---------------- launch ----------------
extern "C" void kernel_launch(void* const* d_in, const int* in_sizes, int n_in,
                              void* d_out, int out_size) {
    const float* buffer_h = (const float*)d_in[0];
    const float* buffer_c = (const float*)d_in[1];
    const int* transitions = (const int*)d_in[2];
    const float* W_buf  = (const float*)d_in[3];
    const float* W_s1   = (const float*)d_in[4];
    const float* W_s2   = (const float*)d_in[5];
    const float* W_lat  = (const float*)d_in[6];
    const float* b_lat  = (const float*)d_in[7];
    const float* W_trans = (const float*)d_in[8];
    const float* b_trans = (const float*)d_in[9];
    const float* W_left = (const float*)d_in[10];
    const float* b_left = (const float*)d_in[11];
    const float* W_right = (const float*)d_in[12];
    const float* W_track = (const float*)d_in[13];
    float* out = (float*)d_out;

    const size_t smem = (size_t)ASZ * sizeof(float); // 66560 B
    cudaFuncSetAttribute(gemm_tf32, cudaFuncAttributeMaxDynamicSharedMemorySize, (int)smem);

    conv_w<<<1024, 256>>>(W_buf, W_s1, W_s2, W_lat, W_left, W_right, W_track);
    idx_kernel<<<1, 64>>>(transitions);
    init_kernel<<<512, 256>>>(buffer_h);

    for (int t = 0; t < Tn; t++) {
        gemm_tf32<<<dim3(N1 / BN, KSPL1), 256, smem>>>(1);
        tracker_kernel<<<Bn, Dn>>>(t, b_lat, W_trans, b_trans, out);
        gemm_tf32<<<dim3(N2 / BN, KSPL2), 256, smem>>>(2);
        compose_kernel<<<Bn, Dn>>>(t, buffer_h, buffer_c, b_left);
    }
    final_kernel<<<Bn, Dn>>>(out);
}

// round 11
// speedup vs baseline: 1.1804x; 1.0280x over previous
#include <cuda_runtime.h>
#include <cstdint>

// ---------------- problem constants ----------------
#define Bn 64
#define Ln 32
#define Dn 768
#define TDn 768
#define Tn 63
#define Sn 32
#define OUTW (Dn + 2 * Tn) // 894

#define K1 3072
#define N1 3072
#define K2 2304
#define N2 3840
#define KSPL1 12
#define KSPL2 9
#define KS 256          // K-slice per CTA (both GEMMs)

// ---------------- device globals ----------------
// W packed in MMA-fragment-linear layout (see pack mapping in conv_w)
__device__ float g_W1[K1 * N1];
__device__ float g_W2[K2 * N2];
__device__ float g_A1[Bn * K1];
__device__ float g_A2[Bn * K2];
__device__ float g_C1[KSPL1 * Bn * N1];
__device__ float g_C2[KSPL2 * Bn * N2];
__device__ float g_sh[Bn * Sn * Dn];
__device__ float g_sc[Bn * Sn * Dn];
__device__ float g_trkc[Bn * TDn];
__device__ int g_bufpos[Tn * Bn];
__device__ int g_p1[Tn * Bn];
__device__ int g_p2[Tn * Bn];
__device__ int g_wpos[Tn * Bn];
__device__ int g_op[Tn * Bn];
__device__ int g_fpos[Bn];

// ---------------- helpers ----------------
__device__ __forceinline__ float to_tf32(float x) {
    uint32_t y;
    asm("cvt.rna.tf32.f32 %0, %1;" : "=r"(y) : "f"(x));
    return __uint_as_float(y);
}
__device__ __forceinline__ float sigm(float x) { return 1.f / (1.f + expf(-x)); }

// ---------------- prologue: precompute shift/reduce indices ----------------
__global__ void idx_kernel(const int* __restrict__ tr) {
    int b = threadIdx.x;
    if (b >= Bn) return;
    int ptr = 0, buft = 0;
    for (int t = 0; t < Tn; t++) {
        int op = tr[b * Tn + t];
        int bp = Ln - 1 - buft;
        bp = bp < 0 ? 0 : (bp > Ln - 1 ? Ln - 1 : bp);
        g_bufpos[t * Bn + b] = bp;
        g_p1[t * Bn + b] = (ptr > 0) ? min(ptr - 1, Sn - 1) : -1;
        g_p2[t * Bn + b] = (ptr > 1) ? min(ptr - 2, Sn - 1) : -1;
        int wp = (op == 0) ? ptr : ptr - 2;
        wp = wp < 0 ? 0 : (wp > Sn - 1 ? Sn - 1 : wp);
        g_wpos[t * Bn + b] = wp;
        g_op[t * Bn + b] = op;
        ptr += (op == 0) ? 1 : ((op == 1) ? -1 : 0);
        buft += (op == 0) ? 1 : 0;
    }
    int fp = ptr - 1;
    fp = fp < 0 ? 0 : (fp > Sn - 1 ? Sn - 1 : fp);
    g_fpos[b] = fp;
}

// ---------------- prologue: concat + tf32-round + MMA-fragment pack ----------------
__device__ __forceinline__ int pack_src(int p, int K, int N) {
    int nblk = p / (K * 32);
    int r = p - nblk * K * 32;
    int k0 = r >> 8;
    int q = r & 255;
    int j = q >> 2, e = q & 3;
    int half = j >> 5, lane = j & 31;
    int g = lane >> 2, tg = lane & 3;
    int nt = half * 2 + (e >> 1);
    int ksrc = k0 * 8 + tg + ((e & 1) ? 4 : 0);
    int nsrc = nblk * 32 + nt * 8 + g;
    return ksrc * N + nsrc;
}

__global__ void conv_w(const float* __restrict__ Wbuf, const float* __restrict__ Ws1,
                       const float* __restrict__ Ws2, const float* __restrict__ Wlat,
                       const float* __restrict__ Wl, const float* __restrict__ Wr,
                       const float* __restrict__ Wt) {
    const int total1 = K1 * N1;
    const int total2 = K2 * N2;
    for (int i = blockIdx.x * blockDim.x + threadIdx.x; i < total1 + total2;
         i += gridDim.x * blockDim.x) {
        if (i < total1) {
            int s = pack_src(i, K1, N1);
            int k = s / N1, n = s - k * N1;
            const float* src = (k < 768) ? Wbuf : (k < 1536) ? Ws1 : (k < 2304) ? Ws2 : Wlat;
            g_W1[i] = to_tf32(src[(k % 768) * N1 + n]);
        } else {
            int j = i - total1;
            int s = pack_src(j, K2, N2);
            int k = s / N2, n = s - k * N2;
            const float* src = (k < 768) ? Wl : (k < 1536) ? Wr : Wt;
            g_W2[j] = to_tf32(src[(k % 768) * N2 + n]);
        }
    }
}

// ---------------- prologue: zero state + build A1/A2 for step 0 ----------------
__global__ void init_kernel(const float* __restrict__ buffer_h) {
    const int n1 = Bn * Sn * Dn;
    const int n2 = 2 * n1;
    const int n3 = n2 + Bn * TDn;
    const int n4 = n3 + Bn * K1;
    const int n5 = n4 + Bn * K2;
    for (int i = blockIdx.x * blockDim.x + threadIdx.x; i < n5; i += gridDim.x * blockDim.x) {
        if (i < n1) g_sh[i] = 0.f;
        else if (i < n2) g_sc[i - n1] = 0.f;
        else if (i < n3) g_trkc[i - n2] = 0.f;
        else if (i < n4) {
            int j = i - n3;
            int b = j / K1, k = j - b * K1;
            g_A1[j] = (k < 768) ? to_tf32(buffer_h[b * Ln * Dn + (Ln - 1) * Dn + k]) : 0.f;
        } else {
            g_A2[i - n4] = 0.f;
        }
    }
}

// ---------------- split-K TF32 GEMM, W streamed from global (packed) ----------------
// block tile 64(M) x 128(N) x KS(256); 8 warps = 2(m) x 4(n), warp tile 32x32.
// A tile (64 x 256) in smem (loaded once); W prefetched 4 stages deep in registers.
#define BM 64
#define BN 128
#define A_ST 260                 // KS + 4 pad (floats)
#define ASZ (BM * A_ST)          // 16640 floats = 66560 B
#define PF 4                     // W register prefetch depth

__device__ __forceinline__ void cp16(uint32_t dst, const void* src) {
    asm volatile("cp.async.cg.shared.global [%0], [%1], 16;" :: "r"(dst), "l"(src));
}

__global__ void __launch_bounds__(256, 2) gemm_tf32(int which) {
    const float* A;
    const float* Wp;
    float* C;
    int ldA, N, Ktot;
    if (which == 1) { A = g_A1; Wp = g_W1; C = g_C1; ldA = K1; N = N1; Ktot = K1; }
    else            { A = g_A2; Wp = g_W2; C = g_C2; ldA = K2; N = N2; Ktot = K2; }

    extern __shared__ float sm[];

    const int tid = threadIdx.x;
    const int kbase0 = blockIdx.y * KS;

    // load A tile 64 x 256 into smem (once)
#pragma unroll
    for (int j = 0; j < 16; j++) {
        int idx = tid + j * 256;
        int r = idx >> 6;               // row 0..63
        int c = (idx & 63) << 2;        // col 0..252
        cp16((uint32_t)__cvta_generic_to_shared(sm + r * A_ST + c), A + (size_t)r * ldA + kbase0 + c);
    }
    asm volatile("cp.async.commit_group;");
    asm volatile("cp.async.wait_group 0;");
    __syncthreads();

    const int lane = tid & 31, w = tid >> 5;
    const int wm = w >> 2, wn = w & 3;      // 2 x 4 warp grid
    const int g = lane >> 2, tg = lane & 3;

    // warp's packed W stream: n_blk = blockIdx.x*4 + wn
    const float4* wp = (const float4*)(Wp + ((size_t)(blockIdx.x * 4 + wn) * Ktot + kbase0) * 32);

    float acc[2][4][4];
#pragma unroll
    for (int mt = 0; mt < 2; mt++)
#pragma unroll
        for (int nt = 0; nt < 4; nt++)
#pragma unroll
            for (int j = 0; j < 4; j++) acc[mt][nt][j] = 0.f;

    const float* as = sm + (wm * 32) * A_ST;
    const int niter = KS / 8;    // 32

    // circular register prefetch buffer, PF stages deep
    float4 buf[PF][2];
#pragma unroll
    for (int s = 0; s < PF; s++) {
        const float4* p = wp + s * 64;
        buf[s][0] = p[lane];
        buf[s][1] = p[32 + lane];
    }

#pragma unroll 4
    for (int it = 0; it < niter; ++it) {
        const int cur = it % PF;   // static after unroll
        float4 b01 = buf[cur][0], b23 = buf[cur][1];
        if (it + PF < niter) {
            const float4* nxt = wp + (it + PF) * 64;
            buf[cur][0] = nxt[lane];
            buf[cur][1] = nxt[32 + lane];
        }
        int kk = it * 8;
        uint32_t a[2][4];
#pragma unroll
        for (int mt = 0; mt < 2; mt++) {
            const float* ar = as + (mt * 16) * A_ST;
            a[mt][0] = __float_as_uint(ar[g * A_ST + kk + tg]);
            a[mt][1] = __float_as_uint(ar[(g + 8) * A_ST + kk + tg]);
            a[mt][2] = __float_as_uint(ar[g * A_ST + kk + tg + 4]);
            a[mt][3] = __float_as_uint(ar[(g + 8) * A_ST + kk + tg + 4]);
        }
        uint32_t bfr[4][2];
        bfr[0][0] = __float_as_uint(b01.x); bfr[0][1] = __float_as_uint(b01.y);
        bfr[1][0] = __float_as_uint(b01.z); bfr[1][1] = __float_as_uint(b01.w);
        bfr[2][0] = __float_as_uint(b23.x); bfr[2][1] = __float_as_uint(b23.y);
        bfr[3][0] = __float_as_uint(b23.z); bfr[3][1] = __float_as_uint(b23.w);
#pragma unroll
        for (int mt = 0; mt < 2; mt++)
#pragma unroll
            for (int nt = 0; nt < 4; nt++) {
                asm volatile(
                    "mma.sync.aligned.m16n8k8.row.col.f32.tf32.tf32.f32 "
                    "{%0,%1,%2,%3}, {%4,%5,%6,%7}, {%8,%9}, {%0,%1,%2,%3};"
                    : "+f"(acc[mt][nt][0]), "+f"(acc[mt][nt][1]),
                      "+f"(acc[mt][nt][2]), "+f"(acc[mt][nt][3])
                    : "r"(a[mt][0]), "r"(a[mt][1]), "r"(a[mt][2]), "r"(a[mt][3]),
                      "r"(bfr[nt][0]), "r"(bfr[nt][1]));
            }
    }

    // epilogue: write split-K partial
    float* Cp = C + (size_t)blockIdx.y * (Bn * N) + blockIdx.x * BN;
#pragma unroll
    for (int mt = 0; mt < 2; mt++) {
        int row0 = wm * 32 + mt * 16 + g;
#pragma unroll
        for (int nt = 0; nt < 4; nt++) {
            int col = wn * 32 + nt * 8 + tg * 2;
            *(float2*)(Cp + (size_t)row0 * N + col) = make_float2(acc[mt][nt][0], acc[mt][nt][1]);
            *(float2*)(Cp + (size_t)(row0 + 8) * N + col) = make_float2(acc[mt][nt][2], acc[mt][nt][3]);
        }
    }
}

// ---------------- per-step: tracker LSTM update + logits ----------------
__global__ void tracker_kernel(int t, const float* __restrict__ b_lat,
                               const float* __restrict__ Wtr, const float* __restrict__ btr,
                               float* __restrict__ out) {
    int b = blockIdx.x;
    int d = threadIdx.x;
    float a = b_lat[d], ii = b_lat[d + 768], ff = b_lat[d + 1536], oo = b_lat[d + 2304];
#pragma unroll
    for (int p = 0; p < KSPL1; p++) {
        const float* cp = g_C1 + (size_t)p * Bn * N1 + (size_t)b * N1;
        a  += cp[d];
        ii += cp[d + 768];
        ff += cp[d + 1536];
        oo += cp[d + 2304];
    }
    float c = tanhf(a) * sigm(ii) + sigm(ff) * g_trkc[b * TDn + d];
    float h = sigm(oo) * tanhf(c);
    g_trkc[b * TDn + d] = c;
    float hr = to_tf32(h);
    g_A2[b * K2 + 1536 + d] = hr;
    g_A1[b * K1 + 2304 + d] = hr;

    float l0 = h * Wtr[d * 2];
    float l1 = h * Wtr[d * 2 + 1];
#pragma unroll
    for (int off = 16; off; off >>= 1) {
        l0 += __shfl_down_sync(0xffffffffu, l0, off);
        l1 += __shfl_down_sync(0xffffffffu, l1, off);
    }
    __shared__ float red[24][2];
    int wid = d >> 5;
    if ((d & 31) == 0) { red[wid][0] = l0; red[wid][1] = l1; }
    __syncthreads();
    if (d < 32) {
        float r0 = (d < 24) ? red[d][0] : 0.f;
        float r1 = (d < 24) ? red[d][1] : 0.f;
#pragma unroll
        for (int off = 16; off; off >>= 1) {
            r0 += __shfl_down_sync(0xffffffffu, r0, off);
            r1 += __shfl_down_sync(0xffffffffu, r1, off);
        }
        if (d == 0) {
            out[(size_t)b * OUTW + Dn + 2 * t]     = r0 + btr[0];
            out[(size_t)b * OUTW + Dn + 2 * t + 1] = r1 + btr[1];
        }
    }
}

// ---------------- per-step: compose + stack update + next-step gather ----------------
__global__ void compose_kernel(int t, const float* __restrict__ buffer_h,
                               const float* __restrict__ buffer_c,
                               const float* __restrict__ b_left) {
    int b = blockIdx.x;
    int d = threadIdx.x;
    int base = t * Bn + b;
    int p1 = g_p1[base], p2 = g_p2[base], wp = g_wpos[base], op = g_op[base], bp = g_bufpos[base];

    float s1c = (p1 >= 0) ? g_sc[(b * Sn + p1) * Dn + d] : 0.f;
    float s2c = (p2 >= 0) ? g_sc[(b * Sn + p2) * Dn + d] : 0.f;

    float gi = b_left[d], gfl = b_left[d + 768], gfr = b_left[d + 1536];
    float go = b_left[d + 2304], gg = b_left[d + 3072];
#pragma unroll
    for (int p = 0; p < KSPL2; p++) {
        const float* cp = g_C2 + (size_t)p * Bn * N2 + (size_t)b * N2;
        gi  += cp[d];
        gfl += cp[d + 768];
        gfr += cp[d + 1536];
        go  += cp[d + 2304];
        gg  += cp[d + 3072];
    }

    float cc = sigm(gfl) * s2c + sigm(gfr) * s1c + sigm(gi) * tanhf(gg);
    float ch = sigm(go) * tanhf(cc);

    float wh, wc;
    if (op == 0) {
        wh = buffer_h[(b * Ln + bp) * Dn + d];
        wc = buffer_c[(b * Ln + bp) * Dn + d];
    } else if (op == 1) {
        wh = ch; wc = cc;
    } else {
        wh = g_sh[(b * Sn + wp) * Dn + d];
        wc = g_sc[(b * Sn + wp) * Dn + d];
    }
    g_sh[(b * Sn + wp) * Dn + d] = wh;
    g_sc[(b * Sn + wp) * Dn + d] = wc;

    if (t + 1 < Tn) {
        int nb = (t + 1) * Bn + b;
        int nbp = g_bufpos[nb], np1 = g_p1[nb], np2 = g_p2[nb];
        float nbh = to_tf32(buffer_h[(b * Ln + nbp) * Dn + d]);
        float ns1 = (np1 >= 0) ? to_tf32(g_sh[(b * Sn + np1) * Dn + d]) : 0.f;
        float ns2 = (np2 >= 0) ? to_tf32(g_sh[(b * Sn + np2) * Dn + d]) : 0.f;
        g_A1[b * K1 + d] = nbh;
        g_A1[b * K1 + 768 + d] = ns1;
        g_A1[b * K1 + 1536 + d] = ns2;
        g_A2[b * K2 + d] = ns2;
        g_A2[b * K2 + 768 + d] = ns1;
    }
}

// ---------------- epilogue: final_h ----------------
__global__ void final_kernel(float* __restrict__ out) {
    int b = blockIdx.x, d = threadIdx.x;
    out[(size_t)b * OUTW + d] = g_sh[(b * Sn + g_fpos[b]) * Dn + d];
}

// ---------------- launch ----------------
extern "C" void kernel_launch(void* const* d_in, const int* in_sizes, int n_in,
                              void* d_out, int out_size) {
    const float* buffer_h = (const float*)d_in[0];
    const float* buffer_c = (const float*)d_in[1];
    const int* transitions = (const int*)d_in[2];
    const float* W_buf  = (const float*)d_in[3];
    const float* W_s1   = (const float*)d_in[4];
    const float* W_s2   = (const float*)d_in[5];
    const float* W_lat  = (const float*)d_in[6];
    const float* b_lat  = (const float*)d_in[7];
    const float* W_trans = (const float*)d_in[8];
    const float* b_trans = (const float*)d_in[9];
    const float* W_left = (const float*)d_in[10];
    const float* b_left = (const float*)d_in[11];
    const float* W_right = (const float*)d_in[12];
    const float* W_track = (const float*)d_in[13];
    float* out = (float*)d_out;

    const size_t smem = (size_t)ASZ * sizeof(float); // 66560 B
    cudaFuncSetAttribute(gemm_tf32, cudaFuncAttributeMaxDynamicSharedMemorySize, (int)smem);

    conv_w<<<1024, 256>>>(W_buf, W_s1, W_s2, W_lat, W_left, W_right, W_track);
    idx_kernel<<<1, 64>>>(transitions);
    init_kernel<<<512, 256>>>(buffer_h);

    for (int t = 0; t < Tn; t++) {
        gemm_tf32<<<dim3(N1 / BN, KSPL1), 256, smem>>>(1);
        tracker_kernel<<<Bn, Dn>>>(t, b_lat, W_trans, b_trans, out);
        gemm_tf32<<<dim3(N2 / BN, KSPL2), 256, smem>>>(2);
        compose_kernel<<<Bn, Dn>>>(t, buffer_h, buffer_c, b_left);
    }
    final_kernel<<<Bn, Dn>>>(out);
}